// round 4
// baseline (speedup 1.0000x reference)
#include <cuda_runtime.h>

// ---------------------------------------------------------------------------
// InferCellV1 on GB300 — fp32 with (a) prefix trick (8x FLOP cut), (b) packed
// fma.rn.f32x2 (2x FMA pipe), (c) BN stats fused into conv kernels,
// (d) float4 combine.
// ---------------------------------------------------------------------------

typedef unsigned long long u64;
#define EPSV 1e-5f

__device__ float  g_C1[(size_t)64 * 64 * 1024];          // conv1 out (16.7 MB)
__device__ float  g_P [(size_t)8 * 64 * 64 * 1024];      // prefix outs (134 MB)
__device__ float  g_N1[(size_t)64 * 64 * 1024];
__device__ float  g_N2[(size_t)64 * 64 * 1024];
__device__ float2 g_part1[64 * 64];                      // [c][b]
__device__ float2 g_part2[8 * 64 * 64];                  // [k][c][b]
__device__ float  g_scale1[64], g_shift1[64];
__device__ float  g_scaleP[8 * 64];
__device__ float  g_biasP[64];
__device__ float  g_m1v[64], g_cmv[64];

__device__ __forceinline__ u64 fma2(u64 a, u64 b, u64 c) {
    u64 d; asm("fma.rn.f32x2 %0, %1, %2, %3;" : "=l"(d) : "l"(a), "l"(b), "l"(c)); return d;
}
__device__ __forceinline__ u64 pack2(float x, float y) {
    u64 d; asm("mov.b64 %0, {%1, %2};" : "=l"(d) : "f"(x), "f"(y)); return d;
}
__device__ __forceinline__ float2 unpack2(u64 v) {
    float2 r; asm("mov.b64 {%0, %1}, %2;" : "=f"(r.x), "=f"(r.y) : "l"(v)); return r;
}

__global__ void prep_kernel(const float* __restrict__ a1, const float* __restrict__ a2) {
    int c = threadIdx.x;
    int g = c >> 3;
    float s1 = 0.f, s2 = 0.f;
    for (int i = g; i < 8; ++i) { s1 += a1[i]; s2 += a2[i]; }
    g_m1v[c] = s1;
    g_cmv[c] = s1 * s2;
}

// ---------------------------------------------------------------------------
// Direct 3x3 conv, one image b x 16 output channels x 32x32 per block.
// Thread: 4 pixels (rows ty+8p, col tx) x 16 oc, accumulated as 8 f32x2 pairs.
// STAGE 1: relu(src) -> conv -> g_C1, fused per-(c,b) stat partials.
// STAGE 2: affine(g_C1) -> conv, prefix P_k emitted per 8-ci group, fused
//          per-(k,c,b) stat partials.
// ---------------------------------------------------------------------------
template <int STAGE, int SRC>
__global__ __launch_bounds__(256, 2)
void conv_kernel(const float* __restrict__ in, const float* __restrict__ w) {
    __shared__ float sIn[9248];        // 8ci x 34x34 halo tile; reused as stat scratch
    __shared__ float sW[1152];         // [ci*9+tap][16 oc]  (oc pairs -> LDS.64)
    __shared__ float sSc[64], sSh[64];

    const int b   = blockIdx.x >> 2;
    const int oc0 = (blockIdx.x & 3) << 4;
    const int t   = threadIdx.x;
    const int tx  = t & 31;
    const int ty  = t >> 5;

    if (STAGE == 2 && t < 64) { sSc[t] = g_scale1[t]; sSh[t] = g_shift1[t]; }

    u64 acc2[4][8];
#pragma unroll
    for (int p = 0; p < 4; ++p)
#pragma unroll
        for (int o2 = 0; o2 < 8; ++o2) acc2[p][o2] = 0ull;

    const float* src = (STAGE == 2) ? g_C1
                     : (SRC == 0)   ? in
                     : (SRC == 1)   ? g_N1
                                    : g_N2;

    for (int cc = 0; cc < 8; ++cc) {
        const int cbase = cc << 3;
        __syncthreads();   // sIn is free to overwrite (covers prior group's readers)

        for (int idx = t; idx < 9248; idx += 256) {
            int ci = idx / 1156;
            int r  = idx - ci * 1156;
            int y  = r / 34;
            int x  = r - y * 34;
            int gy = y - 1, gx = x - 1;
            float v = 0.f;
            if ((unsigned)gy < 32u && (unsigned)gx < 32u) {
                float raw = src[(((size_t)b * 64 + cbase + ci) << 10) + (gy << 5) + gx];
                v = (STAGE == 1) ? fmaxf(raw, 0.f)
                                 : fmaf(raw, sSc[cbase + ci], sSh[cbase + ci]);
            }
            sIn[idx] = v;
        }
        for (int idx = t; idx < 1152; idx += 256) {
            int oc = idx & 15;
            int r  = idx >> 4;          // ci*9 + tap
            int ci = r / 9;
            int tap = r - ci * 9;
            sW[idx] = w[((size_t)(oc0 + oc) * 64 + cbase + ci) * 9 + tap];
        }
        __syncthreads();

#pragma unroll
        for (int ci = 0; ci < 8; ++ci) {
#pragma unroll
            for (int ky = 0; ky < 3; ++ky) {
#pragma unroll
                for (int kx = 0; kx < 3; ++kx) {
                    const float* wrow = &sW[(ci * 9 + ky * 3 + kx) << 4];
                    u64 wp[8];
#pragma unroll
                    for (int o2 = 0; o2 < 8; ++o2)
                        wp[o2] = *reinterpret_cast<const u64*>(wrow + (o2 << 1));
#pragma unroll
                    for (int p = 0; p < 4; ++p) {
                        float iv = sIn[ci * 1156 + (ty + (p << 3) + ky) * 34 + tx + kx];
                        u64 iv2 = pack2(iv, iv);
#pragma unroll
                        for (int o2 = 0; o2 < 8; ++o2)
                            acc2[p][o2] = fma2(iv2, wp[o2], acc2[p][o2]);
                    }
                }
            }
        }

        if (STAGE == 2) {
            // acc2 now holds prefix P_cc. Emit it + fused stat partials.
            float s[16], q[16];
#pragma unroll
            for (int o = 0; o < 16; ++o) { s[o] = 0.f; q[o] = 0.f; }
#pragma unroll
            for (int p = 0; p < 4; ++p) {
                int pix = ((ty + (p << 3)) << 5) + tx;
#pragma unroll
                for (int o2 = 0; o2 < 8; ++o2) {
                    float2 v = unpack2(acc2[p][o2]);
                    size_t base = (((size_t)cc * 64 + b) * 64 + oc0 + (o2 << 1)) * 1024 + pix;
                    g_P[base]        = v.x;
                    g_P[base + 1024] = v.y;
                    s[2 * o2]     += v.x; q[2 * o2]     += v.x * v.x;
                    s[2 * o2 + 1] += v.y; q[2 * o2 + 1] += v.y * v.y;
                }
            }
            __syncthreads();           // done reading sIn for conv
#pragma unroll
            for (int o = 0; o < 16; ++o) { sIn[o * 256 + t] = s[o]; sIn[4096 + o * 256 + t] = q[o]; }
            __syncthreads();
            for (int off = 128; off; off >>= 1) {
                if (t < off) {
#pragma unroll
                    for (int o = 0; o < 16; ++o) {
                        sIn[o * 256 + t]        += sIn[o * 256 + t + off];
                        sIn[4096 + o * 256 + t] += sIn[4096 + o * 256 + t + off];
                    }
                }
                __syncthreads();
            }
            if (t < 16)
                g_part2[(cc * 64 + oc0 + t) * 64 + b] =
                    make_float2(sIn[t * 256], sIn[4096 + t * 256]);
        }
    }

    if (STAGE == 1) {
        float s[16], q[16];
#pragma unroll
        for (int o = 0; o < 16; ++o) { s[o] = 0.f; q[o] = 0.f; }
#pragma unroll
        for (int p = 0; p < 4; ++p) {
            int pix = ((ty + (p << 3)) << 5) + tx;
#pragma unroll
            for (int o2 = 0; o2 < 8; ++o2) {
                float2 v = unpack2(acc2[p][o2]);
                size_t base = (((size_t)b * 64 + oc0 + (o2 << 1)) << 10) + pix;
                g_C1[base]        = v.x;
                g_C1[base + 1024] = v.y;
                s[2 * o2]     += v.x; q[2 * o2]     += v.x * v.x;
                s[2 * o2 + 1] += v.y; q[2 * o2 + 1] += v.y * v.y;
            }
        }
        __syncthreads();
#pragma unroll
        for (int o = 0; o < 16; ++o) { sIn[o * 256 + t] = s[o]; sIn[4096 + o * 256 + t] = q[o]; }
        __syncthreads();
        for (int off = 128; off; off >>= 1) {
            if (t < off) {
#pragma unroll
                for (int o = 0; o < 16; ++o) {
                    sIn[o * 256 + t]        += sIn[o * 256 + t + off];
                    sIn[4096 + o * 256 + t] += sIn[4096 + o * 256 + t + off];
                }
            }
            __syncthreads();
        }
        if (t < 16)
            g_part1[(oc0 + t) * 64 + b] = make_float2(sIn[t * 256], sIn[4096 + t * 256]);
    }
}

// ---------------------------------------------------------------------------
__global__ void fin1_kernel() {  // <<<1,64>>>
    int c = threadIdx.x;
    float s = 0.f, q = 0.f;
    for (int b = 0; b < 64; ++b) { float2 v = g_part1[c * 64 + b]; s += v.x; q += v.y; }
    const float invN = 1.f / 65536.f;
    float mu   = s * invN;
    float var  = q * invN - mu * mu;
    float sc   = rsqrtf(var + EPSV) * g_m1v[c];
    g_scale1[c] = sc;
    g_shift1[c] = -mu * sc;
}

__global__ void fin2_kernel(const float* __restrict__ a2) {  // <<<1,64>>>
    int c = threadIdx.x;
    const float invN = 1.f / 65536.f;
    float bias = 0.f;
    for (int k = 0; k < 8; ++k) {
        float s = 0.f, q = 0.f;
        for (int b = 0; b < 64; ++b) { float2 v = g_part2[(k * 64 + c) * 64 + b]; s += v.x; q += v.y; }
        float mu  = s * invN;
        float var = q * invN - mu * mu;
        float wk  = a2[k] * rsqrtf(var + EPSV);
        g_scaleP[k * 64 + c] = wk;
        bias -= wk * mu;
    }
    g_biasP[c] = bias;
}

// ---------------------------------------------------------------------------
// Combine: out = sum_k scaleP[k,c]*P_k + biasP[c], float4-vectorized.
// MODE 0: -> g_N1
// MODE 1: -> g_N2, + avgpool3(g_N1)*cm (count_include_pad=False)
// MODE 2: -> out,  + xin*cm
// MODE 3: -> out += acc
// ---------------------------------------------------------------------------
template <int MODE>
__global__ __launch_bounds__(256)
void combine_kernel(const float* __restrict__ xin, float* __restrict__ out) {
    int bc = blockIdx.x;
    int b = bc >> 6, c = bc & 63;
    int t = threadIdx.x;
    float sp[8];
#pragma unroll
    for (int k = 0; k < 8; ++k) sp[k] = g_scaleP[k * 64 + c];
    float bias = g_biasP[c];
    float cmv  = g_cmv[c];
    size_t base = ((size_t)b * 64 + c) << 10;
    int p0 = t << 2;

    float4 acc = make_float4(bias, bias, bias, bias);
#pragma unroll
    for (int k = 0; k < 8; ++k) {
        float4 v = *reinterpret_cast<const float4*>(
            &g_P[(((size_t)k * 64 + b) * 64 + c) * 1024 + p0]);
        acc.x = fmaf(sp[k], v.x, acc.x);
        acc.y = fmaf(sp[k], v.y, acc.y);
        acc.z = fmaf(sp[k], v.z, acc.z);
        acc.w = fmaf(sp[k], v.w, acc.w);
    }

    if (MODE == 0) {
        *reinterpret_cast<float4*>(&g_N1[base + p0]) = acc;
    }
    if (MODE == 1) {
        int y = p0 >> 5, x = p0 & 31;
        int y0 = max(y - 1, 0), y1 = min(y + 1, 31);
        float rs[6];
#pragma unroll
        for (int j = 0; j < 6; ++j) {
            int xx = x - 1 + j;
            float v = 0.f;
            if ((unsigned)xx < 32u)
                for (int yy = y0; yy <= y1; ++yy) v += g_N1[base + (yy << 5) + xx];
            rs[j] = v;
        }
        float nr = (float)(y1 - y0 + 1);
        float pool[4];
#pragma unroll
        for (int i = 0; i < 4; ++i) {
            int xi = x + i;
            int c0 = max(xi - 1, 0), c1 = min(xi + 1, 31);
            float cnt = nr * (float)(c1 - c0 + 1);
            pool[i] = (rs[i] + rs[i + 1] + rs[i + 2]) / cnt;
        }
        acc.x += pool[0] * cmv; acc.y += pool[1] * cmv;
        acc.z += pool[2] * cmv; acc.w += pool[3] * cmv;
        *reinterpret_cast<float4*>(&g_N2[base + p0]) = acc;
    }
    if (MODE == 2) {
        float4 xv = *reinterpret_cast<const float4*>(&xin[base + p0]);
        acc.x += xv.x * cmv; acc.y += xv.y * cmv;
        acc.z += xv.z * cmv; acc.w += xv.w * cmv;
        *reinterpret_cast<float4*>(&out[base + p0]) = acc;
    }
    if (MODE == 3) {
        float4 ov = *reinterpret_cast<float4*>(&out[base + p0]);
        acc.x += ov.x; acc.y += ov.y; acc.z += ov.z; acc.w += ov.w;
        *reinterpret_cast<float4*>(&out[base + p0]) = acc;
    }
}

// ---------------------------------------------------------------------------
extern "C" void kernel_launch(void* const* d_in, const int* in_sizes, int n_in,
                              void* d_out, int out_size) {
    (void)in_sizes; (void)n_in; (void)out_size;
    const float* x    = (const float*)d_in[0];
    const float* a1   = (const float*)d_in[1];
    const float* a2   = (const float*)d_in[2];
    const float* W1_0 = (const float*)d_in[3];
    const float* W2_0 = (const float*)d_in[4];
    const float* W1_1 = (const float*)d_in[5];
    const float* W2_1 = (const float*)d_in[6];
    const float* W1_4 = (const float*)d_in[7];
    const float* W2_4 = (const float*)d_in[8];
    const float* W1_5 = (const float*)d_in[9];
    const float* W2_5 = (const float*)d_in[10];
    float* out = (float*)d_out;

    prep_kernel<<<1, 64>>>(a1, a2);

    // n1 = nor_conv(x, W1_0, W2_0)
    conv_kernel<1, 0><<<256, 256>>>(x, W1_0);
    fin1_kernel<<<1, 64>>>();
    conv_kernel<2, 0><<<256, 256>>>(nullptr, W2_0);
    fin2_kernel<<<1, 64>>>(a2);
    combine_kernel<0><<<4096, 256>>>(nullptr, nullptr);

    // n2 = nor_conv(x, W1_1, W2_1) + avgpool3(n1)*cm
    conv_kernel<1, 0><<<256, 256>>>(x, W1_1);
    fin1_kernel<<<1, 64>>>();
    conv_kernel<2, 0><<<256, 256>>>(nullptr, W2_1);
    fin2_kernel<<<1, 64>>>(a2);
    combine_kernel<1><<<4096, 256>>>(nullptr, nullptr);

    // out = x*cm + nor_conv(n1, W1_4, W2_4)
    conv_kernel<1, 1><<<256, 256>>>(nullptr, W1_4);
    fin1_kernel<<<1, 64>>>();
    conv_kernel<2, 0><<<256, 256>>>(nullptr, W2_4);
    fin2_kernel<<<1, 64>>>(a2);
    combine_kernel<2><<<4096, 256>>>(x, out);

    // out += nor_conv(n2, W1_5, W2_5)
    conv_kernel<1, 2><<<256, 256>>>(nullptr, W1_5);
    fin1_kernel<<<1, 64>>>();
    conv_kernel<2, 0><<<256, 256>>>(nullptr, W2_5);
    fin2_kernel<<<1, 64>>>(a2);
    combine_kernel<3><<<4096, 256>>>(nullptr, out);
}

// round 5
// speedup vs baseline: 1.6122x; 1.6122x over previous
#include <cuda_runtime.h>

// ---------------------------------------------------------------------------
// InferCellV1 on GB300 — fp32: prefix trick (8x FLOP cut) + fma.rn.f32x2
// + double-buffered smem staging (overlap LDG with FMA) + division-free
// float4 staging + shfl-butterfly BN stats.
// ---------------------------------------------------------------------------

typedef unsigned long long u64;
#define EPSV 1e-5f

__device__ float  g_C1[(size_t)64 * 64 * 1024];          // conv1 out (16.7 MB)
__device__ float  g_P [(size_t)8 * 64 * 64 * 1024];      // prefix outs (134 MB)
__device__ float  g_N1[(size_t)64 * 64 * 1024];
__device__ float  g_N2[(size_t)64 * 64 * 1024];
__device__ float2 g_part1[64 * 64];                      // [c][b]
__device__ float2 g_part2[8 * 64 * 64];                  // [k][c][b]
__device__ float  g_scale1[64], g_shift1[64];
__device__ float  g_scaleP[8 * 64];
__device__ float  g_biasP[64];
__device__ float  g_m1v[64], g_cmv[64];

__device__ __forceinline__ u64 fma2(u64 a, u64 b, u64 c) {
    u64 d; asm("fma.rn.f32x2 %0, %1, %2, %3;" : "=l"(d) : "l"(a), "l"(b), "l"(c)); return d;
}
__device__ __forceinline__ u64 pack2(float x, float y) {
    u64 d; asm("mov.b64 %0, {%1, %2};" : "=l"(d) : "f"(x), "f"(y)); return d;
}
__device__ __forceinline__ float2 unpack2(u64 v) {
    float2 r; asm("mov.b64 {%0, %1}, %2;" : "=f"(r.x), "=f"(r.y) : "l"(v)); return r;
}

__global__ void prep_kernel(const float* __restrict__ a1, const float* __restrict__ a2) {
    int c = threadIdx.x;
    int g = c >> 3;
    float s1 = 0.f, s2 = 0.f;
    for (int i = g; i < 8; ++i) { s1 += a1[i]; s2 += a2[i]; }
    g_m1v[c] = s1;
    g_cmv[c] = s1 * s2;
}

// Smem layout (floats), dynamic:
//   sIn  : 2 buffers x 8ci x 34rows x 40cols = 21760   (halo: row0/33, col3/36)
//   sW   : 2 buffers x 72 x 16oc             = 2304
//   sStat: 2 parity x 8 warps x 32           = 512
//   sSc  : 64 ; sSh : 64
#define CI_STRIDE   1360     // 34*40
#define BUF_STRIDE  10880    // 8*1360
#define SW_OFF      21760
#define SSTAT_OFF   24064
#define SSC_OFF     24576
#define SSH_OFF     24640
#define SMEM_FLOATS 24704
#define SMEM_BYTES  (SMEM_FLOATS * 4)

// 32-value cross-lane butterfly: lane L ends with sum over lanes of v[L].
__device__ __forceinline__ void warp_reduce32(float* v, int lane) {
#pragma unroll
    for (int d = 16; d >= 1; d >>= 1) {
#pragma unroll
        for (int i = 0; i < d; ++i) {
            float mine  = (lane & d) ? v[i + d] : v[i];
            float give  = (lane & d) ? v[i]     : v[i + d];
            float recv  = __shfl_xor_sync(0xffffffffu, give, d);
            v[i] = mine + recv;
        }
    }
}

// Stage one 8-ci group: interior rows as float4 (halo pre-zeroed) + weights.
template <int STAGE>
__device__ __forceinline__ void stage_group(
    float* __restrict__ dIn, float* __restrict__ dW,
    const float* __restrict__ src, const float* __restrict__ w,
    int b, int oc0, int cbase, int t,
    const float* __restrict__ sSc, const float* __restrict__ sSh)
{
    const int row   = t >> 3;   // 0..31
    const int chunk = t & 7;    // 0..7 (16B chunks)
    const float* sbase = src + (((size_t)b * 64 + cbase) << 10) + (row << 5) + (chunk << 2);
    float* dbase = dIn + (row + 1) * 40 + 4 + (chunk << 2);
#pragma unroll
    for (int ci = 0; ci < 8; ++ci) {
        float4 v = *reinterpret_cast<const float4*>(sbase + ((size_t)ci << 10));
        if (STAGE == 1) {
            v.x = fmaxf(v.x, 0.f); v.y = fmaxf(v.y, 0.f);
            v.z = fmaxf(v.z, 0.f); v.w = fmaxf(v.w, 0.f);
        } else {
            float sc = sSc[cbase + ci], sh = sSh[cbase + ci];
            v.x = fmaf(v.x, sc, sh); v.y = fmaf(v.y, sc, sh);
            v.z = fmaf(v.z, sc, sh); v.w = fmaf(v.w, sc, sh);
        }
        *reinterpret_cast<float4*>(dbase + ci * CI_STRIDE) = v;
    }
    // weights: [r=ci*9+tap][16 oc]
    for (int idx = t; idx < 1152; idx += 256) {
        int oc = idx & 15;
        int r  = idx >> 4;      // 0..71 = ci_local*9 + tap (contiguous in gmem)
        dW[idx] = w[((size_t)(oc0 + oc) * 64 + cbase) * 9 + r];
    }
}

// ---------------------------------------------------------------------------
// Conv: one image b x 16 oc x 32x32 per block; thread: 4 pixel-rows x 16 oc
// as 8 f32x2 accumulators. STAGE 1: relu->conv->g_C1 (+stats at end).
// STAGE 2: affine->conv, prefix P_k per group (+per-group stats).
// ---------------------------------------------------------------------------
template <int STAGE, int SRC>
__global__ __launch_bounds__(256, 2)
void conv_kernel(const float* __restrict__ in, const float* __restrict__ w) {
    extern __shared__ float smem[];
    float* sIn   = smem;
    float* sW    = smem + SW_OFF;
    float* sStat = smem + SSTAT_OFF;
    float* sSc   = smem + SSC_OFF;
    float* sSh   = smem + SSH_OFF;

    const int b    = blockIdx.x >> 2;
    const int oc0  = (blockIdx.x & 3) << 4;
    const int t    = threadIdx.x;
    const int tx   = t & 31;
    const int ty   = t >> 5;
    const int wid  = t >> 5;
    const int lane = t & 31;

    if (STAGE == 2 && t < 64) { sSc[t] = g_scale1[t]; sSh[t] = g_shift1[t]; }

    // one-time halo zero: both buffers, per ci: rows 0,33 (40 ea) + col 3,36 rows1..32
    for (int i = t; i < 2304; i += 256) {
        int bc = i / 144;             // buf*8+ci  (contiguous: bc*CI_STRIDE)
        int r  = i - bc * 144;
        float* base = sIn + bc * CI_STRIDE;
        if (r < 40)      base[r] = 0.f;
        else if (r < 80) base[33 * 40 + (r - 40)] = 0.f;
        else { int rr = r - 80; base[((rr >> 1) + 1) * 40 + ((rr & 1) ? 36 : 3)] = 0.f; }
    }

    u64 acc2[4][8];
#pragma unroll
    for (int p = 0; p < 4; ++p)
#pragma unroll
        for (int o2 = 0; o2 < 8; ++o2) acc2[p][o2] = 0ull;

    const float* src = (STAGE == 2) ? g_C1
                     : (SRC == 0)   ? in
                     : (SRC == 1)   ? g_N1
                                    : g_N2;

    __syncthreads();
    stage_group<STAGE>(sIn, sW, src, w, b, oc0, 0, t, sSc, sSh);
    __syncthreads();

    for (int cc = 0; cc < 8; ++cc) {
        const int cur = cc & 1;
        if (cc < 7)
            stage_group<STAGE>(sIn + (cur ^ 1) * BUF_STRIDE, sW + (cur ^ 1) * 1152,
                               src, w, b, oc0, (cc + 1) << 3, t, sSc, sSh);

        const float* buf = sIn + cur * BUF_STRIDE;
        const float* wb  = sW + cur * 1152;
#pragma unroll 1
        for (int ci = 0; ci < 8; ++ci) {
            const float* bci = buf + ci * CI_STRIDE;
            const float* wci = wb + (ci * 9 << 4);
#pragma unroll
            for (int ky = 0; ky < 3; ++ky) {
#pragma unroll
                for (int kx = 0; kx < 3; ++kx) {
                    const float* wrow = wci + ((ky * 3 + kx) << 4);
                    u64 wp[8];
#pragma unroll
                    for (int o2 = 0; o2 < 8; ++o2)
                        wp[o2] = *reinterpret_cast<const u64*>(wrow + (o2 << 1));
#pragma unroll
                    for (int p = 0; p < 4; ++p) {
                        float iv = bci[(ty + (p << 3) + ky) * 40 + tx + kx + 3];
                        u64 iv2 = pack2(iv, iv);
#pragma unroll
                        for (int o2 = 0; o2 < 8; ++o2)
                            acc2[p][o2] = fma2(iv2, wp[o2], acc2[p][o2]);
                    }
                }
            }
        }

        if (STAGE == 2) {
            // acc2 holds prefix P_cc: emit + stats
            float v[32];
#pragma unroll
            for (int o = 0; o < 32; ++o) v[o] = 0.f;
#pragma unroll
            for (int p = 0; p < 4; ++p) {
                int pix = ((ty + (p << 3)) << 5) + tx;
#pragma unroll
                for (int o2 = 0; o2 < 8; ++o2) {
                    float2 pv = unpack2(acc2[p][o2]);
                    size_t base = (((size_t)cc * 64 + b) * 64 + oc0 + (o2 << 1)) * 1024 + pix;
                    g_P[base]        = pv.x;
                    g_P[base + 1024] = pv.y;
                    v[2 * o2]          += pv.x;
                    v[16 + 2 * o2]     += pv.x * pv.x;
                    v[2 * o2 + 1]      += pv.y;
                    v[16 + 2 * o2 + 1] += pv.y * pv.y;
                }
            }
            warp_reduce32(v, lane);
            sStat[(cc & 1) * 256 + (wid << 5) + lane] = v[0];
        }
        __syncthreads();
        if (STAGE == 2 && t < 32) {
            float s = 0.f;
#pragma unroll
            for (int ww = 0; ww < 8; ++ww) s += sStat[(cc & 1) * 256 + (ww << 5) + lane];
            float qv = __shfl_down_sync(0xffffffffu, s, 16);
            if (lane < 16)
                g_part2[((size_t)cc * 64 + oc0 + lane) * 64 + b] = make_float2(s, qv);
        }
    }

    if (STAGE == 1) {
        float v[32];
#pragma unroll
        for (int o = 0; o < 32; ++o) v[o] = 0.f;
#pragma unroll
        for (int p = 0; p < 4; ++p) {
            int pix = ((ty + (p << 3)) << 5) + tx;
#pragma unroll
            for (int o2 = 0; o2 < 8; ++o2) {
                float2 pv = unpack2(acc2[p][o2]);
                size_t base = (((size_t)b * 64 + oc0 + (o2 << 1)) << 10) + pix;
                g_C1[base]        = pv.x;
                g_C1[base + 1024] = pv.y;
                v[2 * o2]          += pv.x;
                v[16 + 2 * o2]     += pv.x * pv.x;
                v[2 * o2 + 1]      += pv.y;
                v[16 + 2 * o2 + 1] += pv.y * pv.y;
            }
        }
        warp_reduce32(v, lane);
        sStat[(wid << 5) + lane] = v[0];
        __syncthreads();
        if (t < 32) {
            float s = 0.f;
#pragma unroll
            for (int ww = 0; ww < 8; ++ww) s += sStat[(ww << 5) + lane];
            float qv = __shfl_down_sync(0xffffffffu, s, 16);
            if (lane < 16)
                g_part1[(oc0 + lane) * 64 + b] = make_float2(s, qv);
        }
    }
}

// ---------------------------------------------------------------------------
__global__ void fin1_kernel() {  // <<<1,64>>>
    int c = threadIdx.x;
    float s = 0.f, q = 0.f;
    for (int b = 0; b < 64; ++b) { float2 v = g_part1[c * 64 + b]; s += v.x; q += v.y; }
    const float invN = 1.f / 65536.f;
    float mu   = s * invN;
    float var  = q * invN - mu * mu;
    float sc   = rsqrtf(var + EPSV) * g_m1v[c];
    g_scale1[c] = sc;
    g_shift1[c] = -mu * sc;
}

__global__ void fin2_kernel(const float* __restrict__ a2) {  // <<<1,64>>>
    int c = threadIdx.x;
    const float invN = 1.f / 65536.f;
    float bias = 0.f;
    for (int k = 0; k < 8; ++k) {
        float s = 0.f, q = 0.f;
        for (int b = 0; b < 64; ++b) { float2 v = g_part2[(k * 64 + c) * 64 + b]; s += v.x; q += v.y; }
        float mu  = s * invN;
        float var = q * invN - mu * mu;
        float wk  = a2[k] * rsqrtf(var + EPSV);
        g_scaleP[k * 64 + c] = wk;
        bias -= wk * mu;
    }
    g_biasP[c] = bias;
}

// ---------------------------------------------------------------------------
// Combine: out = sum_k scaleP[k,c]*P_k + biasP[c], float4-vectorized.
// MODE 0: -> g_N1 ; MODE 1: -> g_N2 + avgpool3(g_N1)*cm ;
// MODE 2: -> out + xin*cm ; MODE 3: out += acc
// ---------------------------------------------------------------------------
template <int MODE>
__global__ __launch_bounds__(256)
void combine_kernel(const float* __restrict__ xin, float* __restrict__ out) {
    int bc = blockIdx.x;
    int b = bc >> 6, c = bc & 63;
    int t = threadIdx.x;
    float sp[8];
#pragma unroll
    for (int k = 0; k < 8; ++k) sp[k] = g_scaleP[k * 64 + c];
    float bias = g_biasP[c];
    float cmv  = g_cmv[c];
    size_t base = ((size_t)b * 64 + c) << 10;
    int p0 = t << 2;

    float4 acc = make_float4(bias, bias, bias, bias);
#pragma unroll
    for (int k = 0; k < 8; ++k) {
        float4 v = *reinterpret_cast<const float4*>(
            &g_P[(((size_t)k * 64 + b) * 64 + c) * 1024 + p0]);
        acc.x = fmaf(sp[k], v.x, acc.x);
        acc.y = fmaf(sp[k], v.y, acc.y);
        acc.z = fmaf(sp[k], v.z, acc.z);
        acc.w = fmaf(sp[k], v.w, acc.w);
    }

    if (MODE == 0) {
        *reinterpret_cast<float4*>(&g_N1[base + p0]) = acc;
    }
    if (MODE == 1) {
        int y = p0 >> 5, x = p0 & 31;
        int y0 = max(y - 1, 0), y1 = min(y + 1, 31);
        float rs[6];
#pragma unroll
        for (int j = 0; j < 6; ++j) {
            int xx = x - 1 + j;
            float v = 0.f;
            if ((unsigned)xx < 32u)
                for (int yy = y0; yy <= y1; ++yy) v += g_N1[base + (yy << 5) + xx];
            rs[j] = v;
        }
        float nr = (float)(y1 - y0 + 1);
        float pool[4];
#pragma unroll
        for (int i = 0; i < 4; ++i) {
            int xi = x + i;
            int c0 = max(xi - 1, 0), c1 = min(xi + 1, 31);
            float cnt = nr * (float)(c1 - c0 + 1);
            pool[i] = (rs[i] + rs[i + 1] + rs[i + 2]) / cnt;
        }
        acc.x += pool[0] * cmv; acc.y += pool[1] * cmv;
        acc.z += pool[2] * cmv; acc.w += pool[3] * cmv;
        *reinterpret_cast<float4*>(&g_N2[base + p0]) = acc;
    }
    if (MODE == 2) {
        float4 xv = *reinterpret_cast<const float4*>(&xin[base + p0]);
        acc.x += xv.x * cmv; acc.y += xv.y * cmv;
        acc.z += xv.z * cmv; acc.w += xv.w * cmv;
        *reinterpret_cast<float4*>(&out[base + p0]) = acc;
    }
    if (MODE == 3) {
        float4 ov = *reinterpret_cast<float4*>(&out[base + p0]);
        acc.x += ov.x; acc.y += ov.y; acc.z += ov.z; acc.w += ov.w;
        *reinterpret_cast<float4*>(&out[base + p0]) = acc;
    }
}

// ---------------------------------------------------------------------------
extern "C" void kernel_launch(void* const* d_in, const int* in_sizes, int n_in,
                              void* d_out, int out_size) {
    (void)in_sizes; (void)n_in; (void)out_size;
    const float* x    = (const float*)d_in[0];
    const float* a1   = (const float*)d_in[1];
    const float* a2   = (const float*)d_in[2];
    const float* W1_0 = (const float*)d_in[3];
    const float* W2_0 = (const float*)d_in[4];
    const float* W1_1 = (const float*)d_in[5];
    const float* W2_1 = (const float*)d_in[6];
    const float* W1_4 = (const float*)d_in[7];
    const float* W2_4 = (const float*)d_in[8];
    const float* W1_5 = (const float*)d_in[9];
    const float* W2_5 = (const float*)d_in[10];
    float* out = (float*)d_out;

    cudaFuncSetAttribute(conv_kernel<1, 0>, cudaFuncAttributeMaxDynamicSharedMemorySize, SMEM_BYTES);
    cudaFuncSetAttribute(conv_kernel<1, 1>, cudaFuncAttributeMaxDynamicSharedMemorySize, SMEM_BYTES);
    cudaFuncSetAttribute(conv_kernel<1, 2>, cudaFuncAttributeMaxDynamicSharedMemorySize, SMEM_BYTES);
    cudaFuncSetAttribute(conv_kernel<2, 0>, cudaFuncAttributeMaxDynamicSharedMemorySize, SMEM_BYTES);

    prep_kernel<<<1, 64>>>(a1, a2);

    // n1 = nor_conv(x, W1_0, W2_0)
    conv_kernel<1, 0><<<256, 256, SMEM_BYTES>>>(x, W1_0);
    fin1_kernel<<<1, 64>>>();
    conv_kernel<2, 0><<<256, 256, SMEM_BYTES>>>(nullptr, W2_0);
    fin2_kernel<<<1, 64>>>(a2);
    combine_kernel<0><<<4096, 256>>>(nullptr, nullptr);

    // n2 = nor_conv(x, W1_1, W2_1) + avgpool3(n1)*cm
    conv_kernel<1, 0><<<256, 256, SMEM_BYTES>>>(x, W1_1);
    fin1_kernel<<<1, 64>>>();
    conv_kernel<2, 0><<<256, 256, SMEM_BYTES>>>(nullptr, W2_1);
    fin2_kernel<<<1, 64>>>(a2);
    combine_kernel<1><<<4096, 256>>>(nullptr, nullptr);

    // out = x*cm + nor_conv(n1, W1_4, W2_4)
    conv_kernel<1, 1><<<256, 256, SMEM_BYTES>>>(nullptr, W1_4);
    fin1_kernel<<<1, 64>>>();
    conv_kernel<2, 0><<<256, 256, SMEM_BYTES>>>(nullptr, W2_4);
    fin2_kernel<<<1, 64>>>(a2);
    combine_kernel<2><<<4096, 256>>>(x, out);

    // out += nor_conv(n2, W1_5, W2_5)
    conv_kernel<1, 2><<<256, 256, SMEM_BYTES>>>(nullptr, W1_5);
    fin1_kernel<<<1, 64>>>();
    conv_kernel<2, 0><<<256, 256, SMEM_BYTES>>>(nullptr, W2_5);
    fin2_kernel<<<1, 64>>>(a2);
    combine_kernel<3><<<4096, 256>>>(nullptr, out);
}